// round 3
// baseline (speedup 1.0000x reference)
#include <cuda_runtime.h>
#include <math.h>

#define B_TOT 4096
#define T_LEN 32
#define DDIM 15
#define NSTEPS 5
#define DT_C 0.2f
#define RPB 16
#define NBLK (B_TOT / RPB)
#define PAD 18

typedef unsigned long long ull;

// ---------------- packed f32x2 helpers ------------------------------------------
__device__ __forceinline__ ull pack2(float w) {
    ull r;
    asm("mov.b64 %0, {%1, %1};" : "=l"(r) : "r"(__float_as_uint(w)));
    return r;
}
__device__ __forceinline__ void fma2(ull& acc, ull a, ull b) {
    asm("fma.rn.f32x2 %0, %1, %2, %0;" : "+l"(acc) : "l"(a), "l"(b));
}
__device__ __forceinline__ float2 unpack2(ull v) {
    float2 f;
    asm("mov.b64 {%0, %1}, %2;" : "=f"(f.x), "=f"(f.y) : "l"(v));
    return f;
}

// ---------------- weight scratch (device globals) -------------------------------
__device__ float2 g_Wih_rz[25 * 128];
__device__ float  g_Wih_g[25 * 128];
__device__ float2 g_Whh_rz[128 * 128];
__device__ float  g_Whh_g[128 * 128];
__device__ float  g_projT[128 * 64];
__device__ float  g_dr0T[89 * 128];
__device__ float  g_dr1T[128 * 128];
__device__ float  g_dr2T[128 * 128];
__device__ float  g_dr3T[128 * 15];
__device__ float  g_df0T[89 * 128];
__device__ float  g_df1T[128 * 128];
__device__ float  g_df2T[128 * 15];

// ---------------- prep: repack weights ------------------------------------------
__global__ void prep_kernel(const float* __restrict__ wih, const float* __restrict__ whh,
                            const float* __restrict__ proj,
                            const float* __restrict__ d0, const float* __restrict__ d1,
                            const float* __restrict__ d2, const float* __restrict__ d3,
                            const float* __restrict__ f0, const float* __restrict__ f1,
                            const float* __restrict__ f2) {
    int tid = blockIdx.x * blockDim.x + threadIdx.x;
    int nt = gridDim.x * blockDim.x;
    for (int i = tid; i < 25 * 128; i += nt) {
        int k = i >> 7, j = i & 127;
        g_Wih_rz[i] = make_float2(wih[j * 25 + k], wih[(128 + j) * 25 + k]);
        g_Wih_g[i] = wih[(256 + j) * 25 + k];
    }
    for (int i = tid; i < 128 * 128; i += nt) {
        int k = i >> 7, j = i & 127;
        g_Whh_rz[i] = make_float2(whh[j * 128 + k], whh[(128 + j) * 128 + k]);
        g_Whh_g[i] = whh[(256 + j) * 128 + k];
    }
    for (int i = tid; i < 64 * 128; i += nt) { int o = i >> 7, k = i & 127; g_projT[k * 64 + o] = proj[i]; }
    for (int i = tid; i < 128 * 89; i += nt) { int o = i / 89, k = i - o * 89; g_dr0T[k * 128 + o] = d0[i]; }
    for (int i = tid; i < 128 * 128; i += nt) { int o = i >> 7, k = i & 127; g_dr1T[k * 128 + o] = d1[i]; }
    for (int i = tid; i < 128 * 128; i += nt) { int o = i >> 7, k = i & 127; g_dr2T[k * 128 + o] = d2[i]; }
    for (int i = tid; i < 15 * 128; i += nt) { int o = i >> 7, k = i & 127; g_dr3T[k * 15 + o] = d3[i]; }
    for (int i = tid; i < 128 * 89; i += nt) { int o = i / 89, k = i - o * 89; g_df0T[k * 128 + o] = f0[i]; }
    for (int i = tid; i < 128 * 128; i += nt) { int o = i >> 7, k = i & 127; g_df1T[k * 128 + o] = f1[i]; }
    for (int i = tid; i < 15 * 128; i += nt) { int o = i >> 7, k = i & 127; g_df2T[k * 15 + o] = f2[i]; }
}

// ---------------- 5x5 helpers ----------------------------------------------------
__device__ __forceinline__ void mm5(const float* A, const float* Bm, float* Cm) {
#pragma unroll
    for (int i = 0; i < 5; i++) {
#pragma unroll
        for (int jj = 0; jj < 5; jj++) {
            float s = A[i * 5] * Bm[jj];
#pragma unroll
            for (int k = 1; k < 5; k++) s += A[i * 5 + k] * Bm[k * 5 + jj];
            Cm[i * 5 + jj] = s;
        }
    }
}

// geometric SDE update for one element; base = &inp_s[0][r], stride PAD
__device__ void geo_update(float* base) {
    const float is2 = 0.70710678118654752f;
    float S[25];
#pragma unroll
    for (int i = 0; i < 25; i++) S[i] = base[i * PAD];
    float c[15];
#pragma unroll
    for (int i = 0; i < 15; i++) c[i] = base[(89 + i) * PAD];

    float A[25];
    A[0] = c[0]; A[6] = c[1]; A[12] = c[2]; A[18] = c[3]; A[24] = c[4];
    A[1] = A[5] = c[5] * is2;   A[2] = A[10] = c[6] * is2;
    A[3] = A[15] = c[7] * is2;  A[4] = A[20] = c[8] * is2;
    A[7] = A[11] = c[9] * is2;  A[8] = A[16] = c[10] * is2;
    A[9] = A[21] = c[11] * is2; A[13] = A[17] = c[12] * is2;
    A[14] = A[22] = c[13] * is2; A[19] = A[23] = c[14] * is2;

    // L = sqrtm(S), coupled Newton-Schulz on S/tr (spectrum in (0,1])
    float tr = S[0] + S[6] + S[12] + S[18] + S[24];
    float ia = 1.0f / tr;
    float Y[25], Z[25];
#pragma unroll
    for (int i = 0; i < 25; i++) { Y[i] = S[i] * ia; Z[i] = 0.f; }
    Z[0] = Z[6] = Z[12] = Z[18] = Z[24] = 1.f;
    for (int it = 0; it < 12; it++) {
        float P[25]; mm5(Z, Y, P);
        float Tm[25];
#pragma unroll
        for (int i = 0; i < 25; i++) Tm[i] = -0.5f * P[i];
        Tm[0] += 1.5f; Tm[6] += 1.5f; Tm[12] += 1.5f; Tm[18] += 1.5f; Tm[24] += 1.5f;
        float Yn[25], Zn[25];
        mm5(Y, Tm, Yn); mm5(Tm, Z, Zn);
#pragma unroll
        for (int i = 0; i < 25; i++) { Y[i] = Yn[i]; Z[i] = Zn[i]; }
    }
    float sa = sqrtf(tr);
    float L[25];
#pragma unroll
    for (int i = 0; i < 25; i++) L[i] = Y[i] * sa;

    // E = expm(A): 10-term Horner Taylor (||A|| << 1)
    float E[25];
#pragma unroll
    for (int i = 0; i < 25; i++) E[i] = 0.f;
    E[0] = E[6] = E[12] = E[18] = E[24] = 1.f;
#pragma unroll
    for (int k = 10; k >= 1; k--) {
        float AE[25]; mm5(A, E, AE);
        const float invk = 1.0f / (float)k;
#pragma unroll
        for (int i = 0; i < 25; i++) E[i] = AE[i] * invk;
        E[0] += 1.f; E[6] += 1.f; E[12] += 1.f; E[18] += 1.f; E[24] += 1.f;
    }

    float M1[25], M2[25];
    mm5(L, E, M1); mm5(M1, L, M2);
#pragma unroll
    for (int i = 0; i < 5; i++)
#pragma unroll
        for (int jj = 0; jj < 5; jj++)
            base[(i * 5 + jj) * PAD] = 0.5f * (M2[i * 5 + jj] + M2[jj * 5 + i]);
}

// ---------------- fused GRU + SDE kernel: 256 blocks x 256 threads, 16 rows -----
__global__ void __launch_bounds__(256, 2) fused_kernel(
    const float* __restrict__ C, const float* __restrict__ dW,
    const float* __restrict__ gbias, const float* __restrict__ gbias_n,
    const float* __restrict__ proj_b,
    const float* __restrict__ db0, const float* __restrict__ db1,
    const float* __restrict__ db2, const float* __restrict__ db3,
    const float* __restrict__ fb0, const float* __restrict__ fb1,
    const float* __restrict__ fb2, float* __restrict__ out) {
    __shared__ __align__(16) float h_s[128][PAD];     // k-major hidden state
    __shared__ __align__(16) float x_s[25][PAD];      // k-major input
    __shared__ __align__(16) float inp_s[104][PAD];   // [0..24]=sigma [25..88]=ctx [89..103]=coeff
    __shared__ __align__(16) float b1_s[128][PAD];
    __shared__ __align__(16) float b2_s[128][PAD];

    const int tid = threadIdx.x;
    const int b0 = blockIdx.x * RPB;
    const int j = tid & 127, rg = tid >> 7, rbase = rg * 8;

    for (int i = tid; i < 128 * PAD; i += 256) ((float*)h_s)[i] = 0.f;

    const float br = gbias[j], bz = gbias[128 + j], bg = gbias[256 + j], bn = gbias_n[j];
    const ull br2 = pack2(br), bz2 = pack2(bz), bg2 = pack2(bg);

    // ================= GRU encoder =================
    for (int t = 0; t < T_LEN; t++) {
        __syncthreads();
        for (int i = tid; i < RPB * 25; i += 256) {
            int r = i / 25, k = i - r * 25;
            int ii = k / 5, jj = k - ii * 5;
            const float* p = C + ((size_t)(b0 + r) * T_LEN + t) * 25;
            x_s[k][r] = 0.5f * (p[ii * 5 + jj] + p[jj * 5 + ii]);
        }
        __syncthreads();

        ull Ar[4], Az[4], Ag[4], Ah[4];
#pragma unroll
        for (int p = 0; p < 4; p++) { Ar[p] = br2; Az[p] = bz2; Ag[p] = bg2; Ah[p] = 0ull; }

#pragma unroll 5
        for (int k = 0; k < 25; k++) {
            float2 wrz = g_Wih_rz[k * 128 + j];
            float wgv = g_Wih_g[k * 128 + j];
            ull wr2 = pack2(wrz.x), wz2 = pack2(wrz.y), wg2 = pack2(wgv);
            const ull* xp = (const ull*)&x_s[k][rbase];
#pragma unroll
            for (int p = 0; p < 4; p++) {
                ull x2 = xp[p];
                fma2(Ar[p], wr2, x2); fma2(Az[p], wz2, x2); fma2(Ag[p], wg2, x2);
            }
        }
#pragma unroll 4
        for (int k = 0; k < 128; k++) {
            float2 wrz = g_Whh_rz[k * 128 + j];
            float wgv = g_Whh_g[k * 128 + j];
            ull wr2 = pack2(wrz.x), wz2 = pack2(wrz.y), wg2 = pack2(wgv);
            const ull* hp = (const ull*)&h_s[k][rbase];
#pragma unroll
            for (int p = 0; p < 4; p++) {
                ull h2 = hp[p];
                fma2(Ar[p], wr2, h2); fma2(Az[p], wz2, h2); fma2(Ah[p], wg2, h2);
            }
        }

        float hnew[8];
        {
            const ull* hj = (const ull*)&h_s[j][rbase];
#pragma unroll
            for (int p = 0; p < 4; p++) {
                float2 fr = unpack2(Ar[p]), fz = unpack2(Az[p]);
                float2 fg = unpack2(Ag[p]), fh = unpack2(Ah[p]);
                float2 ho = unpack2(hj[p]);
                {
                    float r = 1.f / (1.f + __expf(-fr.x));
                    float z = 1.f / (1.f + __expf(-fz.x));
                    float g = tanhf(fg.x + r * (fh.x + bn));
                    hnew[2 * p] = (1.f - z) * g + z * ho.x;
                }
                {
                    float r = 1.f / (1.f + __expf(-fr.y));
                    float z = 1.f / (1.f + __expf(-fz.y));
                    float g = tanhf(fg.y + r * (fh.y + bn));
                    hnew[2 * p + 1] = (1.f - z) * g + z * ho.y;
                }
            }
        }
        __syncthreads();
#pragma unroll
        for (int m = 0; m < 8; m++) h_s[j][rbase + m] = hnew[m];
    }
    __syncthreads();

    // ================= projection: ctx -> inp_s[25..88] =================
    {
        const int jc = tid & 63, rg2 = tid >> 6;
        const float pb = proj_b[jc];
#pragma unroll
        for (int m = 0; m < 4; m++) {
            int r = rg2 * 4 + m;
            float acc = pb;
#pragma unroll 4
            for (int k = 0; k < 128; k++) acc += h_s[k][r] * g_projT[k * 64 + jc];
            inp_s[25 + jc][r] = acc;
        }
    }
    // sigma_0 = sym(context[:, T-1])
    for (int i = tid; i < RPB * 25; i += 256) {
        int r = i / 25, k = i - r * 25;
        int ii = k / 5, jj = k - ii * 5;
        const float* p = C + ((size_t)(b0 + r) * T_LEN + (T_LEN - 1)) * 25;
        inp_s[k][r] = 0.5f * (p[ii * 5 + jj] + p[jj * 5 + ii]);
    }
    __syncthreads();

    const float v_db0 = db0[j], v_db1 = db1[j], v_db2 = db2[j];
    const float v_fb0 = fb0[j], v_fb1 = fb1[j];

    // ================= SDE steps =================
    for (int step = 0; step < NSTEPS; step++) {
        // drift L0: b1 = silu(inp @ W0^T + b0)
        {
            ull acc[4];
#pragma unroll
            for (int p = 0; p < 4; p++) acc[p] = pack2(v_db0);
#pragma unroll 4
            for (int k = 0; k < 89; k++) {
                ull w2 = pack2(g_dr0T[k * 128 + j]);
                const ull* sp = (const ull*)&inp_s[k][rbase];
#pragma unroll
                for (int p = 0; p < 4; p++) fma2(acc[p], w2, sp[p]);
            }
#pragma unroll
            for (int p = 0; p < 4; p++) {
                float2 f = unpack2(acc[p]);
                b1_s[j][rbase + 2 * p] = f.x / (1.f + __expf(-f.x));
                b1_s[j][rbase + 2 * p + 1] = f.y / (1.f + __expf(-f.y));
            }
        }
        __syncthreads();
        // drift L1
        {
            ull acc[4];
#pragma unroll
            for (int p = 0; p < 4; p++) acc[p] = pack2(v_db1);
#pragma unroll 4
            for (int k = 0; k < 128; k++) {
                ull w2 = pack2(g_dr1T[k * 128 + j]);
                const ull* sp = (const ull*)&b1_s[k][rbase];
#pragma unroll
                for (int p = 0; p < 4; p++) fma2(acc[p], w2, sp[p]);
            }
#pragma unroll
            for (int p = 0; p < 4; p++) {
                float2 f = unpack2(acc[p]);
                b2_s[j][rbase + 2 * p] = f.x / (1.f + __expf(-f.x));
                b2_s[j][rbase + 2 * p + 1] = f.y / (1.f + __expf(-f.y));
            }
        }
        __syncthreads();
        // drift L2
        {
            ull acc[4];
#pragma unroll
            for (int p = 0; p < 4; p++) acc[p] = pack2(v_db2);
#pragma unroll 4
            for (int k = 0; k < 128; k++) {
                ull w2 = pack2(g_dr2T[k * 128 + j]);
                const ull* sp = (const ull*)&b2_s[k][rbase];
#pragma unroll
                for (int p = 0; p < 4; p++) fma2(acc[p], w2, sp[p]);
            }
#pragma unroll
            for (int p = 0; p < 4; p++) {
                float2 f = unpack2(acc[p]);
                b1_s[j][rbase + 2 * p] = f.x / (1.f + __expf(-f.x));
                b1_s[j][rbase + 2 * p + 1] = f.y / (1.f + __expf(-f.y));
            }
        }
        __syncthreads();
        // drift L3 (240 items) + diff L0 (all threads); disjoint smem regions
        {
            if (tid < 240) {
                int r = tid / 15, k = tid - r * 15;
                float acc = db3[k];
#pragma unroll 4
                for (int cc = 0; cc < 128; cc++) acc += b1_s[cc][r] * g_dr3T[cc * 15 + k];
                inp_s[89 + k][r] = acc;   // raw drift_c
            }
            ull acc[4];
#pragma unroll
            for (int p = 0; p < 4; p++) acc[p] = pack2(v_fb0);
#pragma unroll 4
            for (int k = 0; k < 89; k++) {
                ull w2 = pack2(g_df0T[k * 128 + j]);
                const ull* sp = (const ull*)&inp_s[k][rbase];
#pragma unroll
                for (int p = 0; p < 4; p++) fma2(acc[p], w2, sp[p]);
            }
#pragma unroll
            for (int p = 0; p < 4; p++) {
                float2 f = unpack2(acc[p]);
                b2_s[j][rbase + 2 * p] = f.x / (1.f + __expf(-f.x));
                b2_s[j][rbase + 2 * p + 1] = f.y / (1.f + __expf(-f.y));
            }
        }
        __syncthreads();
        // diff L1
        {
            ull acc[4];
#pragma unroll
            for (int p = 0; p < 4; p++) acc[p] = pack2(v_fb1);
#pragma unroll 4
            for (int k = 0; k < 128; k++) {
                ull w2 = pack2(g_df1T[k * 128 + j]);
                const ull* sp = (const ull*)&b2_s[k][rbase];
#pragma unroll
                for (int p = 0; p < 4; p++) fma2(acc[p], w2, sp[p]);
            }
#pragma unroll
            for (int p = 0; p < 4; p++) {
                float2 f = unpack2(acc[p]);
                b1_s[j][rbase + 2 * p] = f.x / (1.f + __expf(-f.x));
                b1_s[j][rbase + 2 * p + 1] = f.y / (1.f + __expf(-f.y));
            }
        }
        __syncthreads();
        // diff L2 + combine: coeff = drift*DT + softplus(.)*dW
        if (tid < 240) {
            int r = tid / 15, k = tid - r * 15;
            float acc = fb2[k];
#pragma unroll 4
            for (int cc = 0; cc < 128; cc++) acc += b1_s[cc][r] * g_df2T[cc * 15 + k];
            float sp = (acc > 20.f) ? acc : log1pf(__expf(acc));
            float dwv = dW[((size_t)(b0 + r) * NSTEPS + step) * DDIM + k];
            inp_s[89 + k][r] = inp_s[89 + k][r] * DT_C + sp * dwv;
        }
        __syncthreads();
        // geometric update: 16 elements on lanes 0..15 of warp 0
        if (tid < RPB) geo_update(&inp_s[0][tid]);
        __syncthreads();
    }

    for (int i = tid; i < RPB * 25; i += 256) {
        int r = i / 25, k = i - r * 25;
        out[(size_t)(b0 + r) * 25 + k] = inp_s[k][r];
    }
}

// ---------------- launch ---------------------------------------------------------
extern "C" void kernel_launch(void* const* d_in, const int* in_sizes, int n_in,
                              void* d_out, int out_size) {
    const float* ctx_spd = (const float*)d_in[0];
    const float* dWp     = (const float*)d_in[1];
    const float* wih     = (const float*)d_in[2];
    const float* whh     = (const float*)d_in[3];
    const float* gbias   = (const float*)d_in[4];
    const float* gbias_n = (const float*)d_in[5];
    const float* projw   = (const float*)d_in[6];
    const float* projb   = (const float*)d_in[7];
    const float* dw0 = (const float*)d_in[8];  const float* db0 = (const float*)d_in[9];
    const float* dw1 = (const float*)d_in[10]; const float* db1 = (const float*)d_in[11];
    const float* dw2 = (const float*)d_in[12]; const float* db2 = (const float*)d_in[13];
    const float* dw3 = (const float*)d_in[14]; const float* db3 = (const float*)d_in[15];
    const float* fw0 = (const float*)d_in[16]; const float* fb0 = (const float*)d_in[17];
    const float* fw1 = (const float*)d_in[18]; const float* fb1 = (const float*)d_in[19];
    const float* fw2 = (const float*)d_in[20]; const float* fb2 = (const float*)d_in[21];
    float* out = (float*)d_out;

    prep_kernel<<<64, 256>>>(wih, whh, projw, dw0, dw1, dw2, dw3, fw0, fw1, fw2);
    fused_kernel<<<NBLK, 256>>>(ctx_spd, dWp, gbias, gbias_n, projb,
                                db0, db1, db2, db3, fb0, fb1, fb2, out);
}

// round 4
// speedup vs baseline: 1.6771x; 1.6771x over previous
#include <cuda_runtime.h>
#include <cuda_bf16.h>
#include <math.h>

#define B_TOT 4096
#define T_LEN 32
#define DDIM 15
#define NSTEPS 5
#define DT_C 0.2f
#define RPB 16
#define NBLK (B_TOT / RPB)
#define PAD 20

typedef unsigned long long ull;
typedef unsigned int u32;

// ---------------- packed f32x2 helpers ------------------------------------------
__device__ __forceinline__ void fma2(ull& acc, ull a, ull b) {
    asm("fma.rn.f32x2 %0, %1, %2, %0;" : "+l"(acc) : "l"(a), "l"(b));
}
__device__ __forceinline__ ull pack2f(float w) {
    ull r; asm("mov.b64 %0, {%1, %1};" : "=l"(r) : "r"(__float_as_uint(w))); return r;
}
// bf16 in low 16 bits of u -> f32 broadcast pair (f32 bits = bf16 bits << 16)
__device__ __forceinline__ ull bplo(u32 u) {
    u32 f = u << 16; ull r; asm("mov.b64 %0, {%1, %1};" : "=l"(r) : "r"(f)); return r;
}
// bf16 in high 16 bits of u -> f32 broadcast pair
__device__ __forceinline__ ull bphi(u32 u) {
    u32 f = u & 0xFFFF0000u; ull r; asm("mov.b64 %0, {%1, %1};" : "=l"(r) : "r"(f)); return r;
}
__device__ __forceinline__ float2 unpack2(ull v) {
    float2 f; asm("mov.b64 {%0, %1}, %2;" : "=f"(f.x), "=f"(f.y) : "l"(v)); return f;
}
__device__ __forceinline__ float fsig(float x) { return 1.f / (1.f + __expf(-x)); }
__device__ __forceinline__ float ftanh(float x) { return 1.f - 2.f / (1.f + __expf(2.f * x)); }

// ---------------- weight scratch (device globals) -------------------------------
__device__ u32 g_Wih_rz[26 * 128];   // [k][j]: lo=w_r bf16, hi=w_z bf16 (k=25 zero pad)
__device__ u32 g_Wih_g[13 * 128];    // [kp][j]: lo=w_g[2kp], hi=w_g[2kp+1]
__device__ u32 g_Whh_rz[128 * 128];
__device__ u32 g_Whh_g[64 * 128];
__device__ u32 g_dr0P[45 * 128];     // [kp][j]: lo=w[2kp], hi=w[2kp+1] (k=89 zero pad)
__device__ u32 g_dr1P[64 * 128];
__device__ u32 g_dr2P[64 * 128];
__device__ u32 g_df0P[45 * 128];
__device__ u32 g_df1P[64 * 128];
__device__ float g_dr3T[128 * 15];
__device__ float g_df2T[128 * 15];
__device__ float g_projT[128 * 64];

__device__ __forceinline__ u32 bfbits(float w) {
    __nv_bfloat16 h = __float2bfloat16(w);
    return (u32)__bfloat16_as_ushort(h);
}

// ---------------- prep: repack/quantize weights ---------------------------------
__global__ void prep_kernel(const float* __restrict__ wih, const float* __restrict__ whh,
                            const float* __restrict__ proj,
                            const float* __restrict__ d0, const float* __restrict__ d1,
                            const float* __restrict__ d2, const float* __restrict__ d3,
                            const float* __restrict__ f0, const float* __restrict__ f1,
                            const float* __restrict__ f2) {
    int tid = blockIdx.x * blockDim.x + threadIdx.x;
    int nt = gridDim.x * blockDim.x;
    for (int i = tid; i < 26 * 128; i += nt) {
        int k = i >> 7, j = i & 127;
        float wr = (k < 25) ? wih[j * 25 + k] : 0.f;
        float wz = (k < 25) ? wih[(128 + j) * 25 + k] : 0.f;
        g_Wih_rz[i] = bfbits(wr) | (bfbits(wz) << 16);
    }
    for (int i = tid; i < 13 * 128; i += nt) {
        int kp = i >> 7, j = i & 127;
        int k0 = 2 * kp, k1 = 2 * kp + 1;
        float g0 = (k0 < 25) ? wih[(256 + j) * 25 + k0] : 0.f;
        float g1 = (k1 < 25) ? wih[(256 + j) * 25 + k1] : 0.f;
        g_Wih_g[i] = bfbits(g0) | (bfbits(g1) << 16);
    }
    for (int i = tid; i < 128 * 128; i += nt) {
        int k = i >> 7, j = i & 127;
        g_Whh_rz[i] = bfbits(whh[j * 128 + k]) | (bfbits(whh[(128 + j) * 128 + k]) << 16);
    }
    for (int i = tid; i < 64 * 128; i += nt) {
        int kp = i >> 7, j = i & 127;
        g_Whh_g[i] = bfbits(whh[(256 + j) * 128 + 2 * kp]) |
                     (bfbits(whh[(256 + j) * 128 + 2 * kp + 1]) << 16);
    }
    for (int i = tid; i < 45 * 128; i += nt) {
        int kp = i >> 7, j = i & 127;
        int k0 = 2 * kp, k1 = 2 * kp + 1;
        float a0 = (k0 < 89) ? d0[j * 89 + k0] : 0.f;
        float a1 = (k1 < 89) ? d0[j * 89 + k1] : 0.f;
        g_dr0P[i] = bfbits(a0) | (bfbits(a1) << 16);
        float c0 = (k0 < 89) ? f0[j * 89 + k0] : 0.f;
        float c1 = (k1 < 89) ? f0[j * 89 + k1] : 0.f;
        g_df0P[i] = bfbits(c0) | (bfbits(c1) << 16);
    }
    for (int i = tid; i < 64 * 128; i += nt) {
        int kp = i >> 7, j = i & 127;
        g_dr1P[i] = bfbits(d1[j * 128 + 2 * kp]) | (bfbits(d1[j * 128 + 2 * kp + 1]) << 16);
        g_dr2P[i] = bfbits(d2[j * 128 + 2 * kp]) | (bfbits(d2[j * 128 + 2 * kp + 1]) << 16);
        g_df1P[i] = bfbits(f1[j * 128 + 2 * kp]) | (bfbits(f1[j * 128 + 2 * kp + 1]) << 16);
    }
    for (int i = tid; i < 15 * 128; i += nt) { int o = i >> 7, k = i & 127; g_dr3T[k * 15 + o] = d3[i]; }
    for (int i = tid; i < 15 * 128; i += nt) { int o = i >> 7, k = i & 127; g_df2T[k * 15 + o] = f2[i]; }
    for (int i = tid; i < 64 * 128; i += nt) { int o = i >> 7, k = i & 127; g_projT[k * 64 + o] = proj[i]; }
}

// ---------------- 5x5 helpers ----------------------------------------------------
__device__ __forceinline__ void mm5(const float* A, const float* Bm, float* Cm) {
#pragma unroll
    for (int i = 0; i < 5; i++) {
#pragma unroll
        for (int jj = 0; jj < 5; jj++) {
            float s = A[i * 5] * Bm[jj];
#pragma unroll
            for (int k = 1; k < 5; k++) s += A[i * 5 + k] * Bm[k * 5 + jj];
            Cm[i * 5 + jj] = s;
        }
    }
}

__device__ void geo_update(float* base) {
    const float is2 = 0.70710678118654752f;
    float S[25];
#pragma unroll
    for (int i = 0; i < 25; i++) S[i] = base[i * PAD];
    float c[15];
#pragma unroll
    for (int i = 0; i < 15; i++) c[i] = base[(89 + i) * PAD];

    float A[25];
    A[0] = c[0]; A[6] = c[1]; A[12] = c[2]; A[18] = c[3]; A[24] = c[4];
    A[1] = A[5] = c[5] * is2;   A[2] = A[10] = c[6] * is2;
    A[3] = A[15] = c[7] * is2;  A[4] = A[20] = c[8] * is2;
    A[7] = A[11] = c[9] * is2;  A[8] = A[16] = c[10] * is2;
    A[9] = A[21] = c[11] * is2; A[13] = A[17] = c[12] * is2;
    A[14] = A[22] = c[13] * is2; A[19] = A[23] = c[14] * is2;

    float tr = S[0] + S[6] + S[12] + S[18] + S[24];
    float ia = 1.0f / tr;
    float Y[25], Z[25];
#pragma unroll
    for (int i = 0; i < 25; i++) { Y[i] = S[i] * ia; Z[i] = 0.f; }
    Z[0] = Z[6] = Z[12] = Z[18] = Z[24] = 1.f;
    for (int it = 0; it < 12; it++) {
        float P[25]; mm5(Z, Y, P);
        float Tm[25];
#pragma unroll
        for (int i = 0; i < 25; i++) Tm[i] = -0.5f * P[i];
        Tm[0] += 1.5f; Tm[6] += 1.5f; Tm[12] += 1.5f; Tm[18] += 1.5f; Tm[24] += 1.5f;
        float Yn[25], Zn[25];
        mm5(Y, Tm, Yn); mm5(Tm, Z, Zn);
#pragma unroll
        for (int i = 0; i < 25; i++) { Y[i] = Yn[i]; Z[i] = Zn[i]; }
    }
    float sa = sqrtf(tr);
    float L[25];
#pragma unroll
    for (int i = 0; i < 25; i++) L[i] = Y[i] * sa;

    float E[25];
#pragma unroll
    for (int i = 0; i < 25; i++) E[i] = 0.f;
    E[0] = E[6] = E[12] = E[18] = E[24] = 1.f;
#pragma unroll
    for (int k = 10; k >= 1; k--) {
        float AE[25]; mm5(A, E, AE);
        const float invk = 1.0f / (float)k;
#pragma unroll
        for (int i = 0; i < 25; i++) E[i] = AE[i] * invk;
        E[0] += 1.f; E[6] += 1.f; E[12] += 1.f; E[18] += 1.f; E[24] += 1.f;
    }

    float M1[25], M2[25];
    mm5(L, E, M1); mm5(M1, L, M2);
#pragma unroll
    for (int i = 0; i < 5; i++)
#pragma unroll
        for (int jj = 0; jj < 5; jj++)
            base[(i * 5 + jj) * PAD] = 0.5f * (M2[i * 5 + jj] + M2[jj * 5 + i]);
}

// ---------------- MLP layer helper (bf16 weights, f32x2 math) --------------------
__device__ __forceinline__ void mlp_layer(const u32* __restrict__ Wp, int npairs,
                                          const float (*in_s)[PAD], float (*out_s)[PAD],
                                          float bias, int j, int rbase) {
    ull acc[4];
    ull b2 = pack2f(bias);
#pragma unroll
    for (int p = 0; p < 4; p++) acc[p] = b2;
#pragma unroll 8
    for (int kp = 0; kp < npairs; kp++) {
        int k = 2 * kp;
        u32 ww = Wp[kp * 128 + j];
        ull w0 = bplo(ww), w1 = bphi(ww);
        ulonglong2 v0 = *(const ulonglong2*)&in_s[k][rbase];
        ulonglong2 v1 = *(const ulonglong2*)&in_s[k][rbase + 4];
        ulonglong2 u0 = *(const ulonglong2*)&in_s[k + 1][rbase];
        ulonglong2 u1 = *(const ulonglong2*)&in_s[k + 1][rbase + 4];
        fma2(acc[0], w0, v0.x); fma2(acc[1], w0, v0.y);
        fma2(acc[2], w0, v1.x); fma2(acc[3], w0, v1.y);
        fma2(acc[0], w1, u0.x); fma2(acc[1], w1, u0.y);
        fma2(acc[2], w1, u1.x); fma2(acc[3], w1, u1.y);
    }
#pragma unroll
    for (int p = 0; p < 4; p++) {
        float2 f = unpack2(acc[p]);
        out_s[j][rbase + 2 * p] = f.x * fsig(f.x);
        out_s[j][rbase + 2 * p + 1] = f.y * fsig(f.y);
    }
}

// ---------------- fused GRU + SDE kernel ----------------------------------------
__global__ void __launch_bounds__(256, 2) fused_kernel(
    const float* __restrict__ C, const float* __restrict__ dW,
    const float* __restrict__ gbias, const float* __restrict__ gbias_n,
    const float* __restrict__ proj_b,
    const float* __restrict__ db0, const float* __restrict__ db1,
    const float* __restrict__ db2, const float* __restrict__ db3,
    const float* __restrict__ fb0, const float* __restrict__ fb1,
    const float* __restrict__ fb2, float* __restrict__ out) {
    __shared__ __align__(16) float h_s[128][PAD];
    __shared__ __align__(16) float x_s[26][PAD];
    __shared__ __align__(16) float inp_s[104][PAD];
    __shared__ __align__(16) float b1_s[128][PAD];
    __shared__ __align__(16) float b2_s[128][PAD];

    const int tid = threadIdx.x;
    const int b0 = blockIdx.x * RPB;
    const int j = tid & 127, rg = tid >> 7, rbase = rg * 8;

    for (int i = tid; i < 128 * PAD; i += 256) ((float*)h_s)[i] = 0.f;
    for (int i = tid; i < 26 * PAD; i += 256) ((float*)x_s)[i] = 0.f;
    // zero coeff rows (read with zero weight by L0 pair 44 before first write)
    for (int i = tid; i < 15 * PAD; i += 256) (&inp_s[89][0])[i] = 0.f;

    const float br = gbias[j], bz = gbias[128 + j], bg = gbias[256 + j], bn = gbias_n[j];
    const ull br2 = pack2f(br), bz2 = pack2f(bz), bg2 = pack2f(bg);

    // ================= GRU encoder =================
    for (int t = 0; t < T_LEN; t++) {
        __syncthreads();
        for (int i = tid; i < RPB * 25; i += 256) {
            int r = i / 25, k = i - r * 25;
            int ii = k / 5, jj = k - ii * 5;
            const float* p = C + ((size_t)(b0 + r) * T_LEN + t) * 25;
            x_s[k][r] = 0.5f * (p[ii * 5 + jj] + p[jj * 5 + ii]);
        }
        __syncthreads();

        ull Ar[4], Az[4], Ag[4], Ah[4];
#pragma unroll
        for (int p = 0; p < 4; p++) { Ar[p] = br2; Az[p] = bz2; Ag[p] = bg2; Ah[p] = 0ull; }

        // input part (13 k-pairs; pair 12 has zero-padded k=25)
#pragma unroll
        for (int kp = 0; kp < 13; kp++) {
            int k = 2 * kp;
            u32 rz0 = g_Wih_rz[k * 128 + j];
            u32 rz1 = g_Wih_rz[(k + 1) * 128 + j];
            u32 gg = g_Wih_g[kp * 128 + j];
            ull wr0 = bplo(rz0), wz0 = bphi(rz0), wg0 = bplo(gg);
            ull wr1 = bplo(rz1), wz1 = bphi(rz1), wg1 = bphi(gg);
            ulonglong2 v0 = *(const ulonglong2*)&x_s[k][rbase];
            ulonglong2 v1 = *(const ulonglong2*)&x_s[k][rbase + 4];
            ulonglong2 u0 = *(const ulonglong2*)&x_s[k + 1][rbase];
            ulonglong2 u1 = *(const ulonglong2*)&x_s[k + 1][rbase + 4];
            fma2(Ar[0], wr0, v0.x); fma2(Az[0], wz0, v0.x); fma2(Ag[0], wg0, v0.x);
            fma2(Ar[1], wr0, v0.y); fma2(Az[1], wz0, v0.y); fma2(Ag[1], wg0, v0.y);
            fma2(Ar[2], wr0, v1.x); fma2(Az[2], wz0, v1.x); fma2(Ag[2], wg0, v1.x);
            fma2(Ar[3], wr0, v1.y); fma2(Az[3], wz0, v1.y); fma2(Ag[3], wg0, v1.y);
            fma2(Ar[0], wr1, u0.x); fma2(Az[0], wz1, u0.x); fma2(Ag[0], wg1, u0.x);
            fma2(Ar[1], wr1, u0.y); fma2(Az[1], wz1, u0.y); fma2(Ag[1], wg1, u0.y);
            fma2(Ar[2], wr1, u1.x); fma2(Az[2], wz1, u1.x); fma2(Ag[2], wg1, u1.x);
            fma2(Ar[3], wr1, u1.y); fma2(Az[3], wz1, u1.y); fma2(Ag[3], wg1, u1.y);
        }
        // hidden part (64 k-pairs)
#pragma unroll 8
        for (int kp = 0; kp < 64; kp++) {
            int k = 2 * kp;
            u32 rz0 = g_Whh_rz[k * 128 + j];
            u32 rz1 = g_Whh_rz[(k + 1) * 128 + j];
            u32 gg = g_Whh_g[kp * 128 + j];
            ull wr0 = bplo(rz0), wz0 = bphi(rz0), wg0 = bplo(gg);
            ull wr1 = bplo(rz1), wz1 = bphi(rz1), wg1 = bphi(gg);
            ulonglong2 v0 = *(const ulonglong2*)&h_s[k][rbase];
            ulonglong2 v1 = *(const ulonglong2*)&h_s[k][rbase + 4];
            ulonglong2 u0 = *(const ulonglong2*)&h_s[k + 1][rbase];
            ulonglong2 u1 = *(const ulonglong2*)&h_s[k + 1][rbase + 4];
            fma2(Ar[0], wr0, v0.x); fma2(Az[0], wz0, v0.x); fma2(Ah[0], wg0, v0.x);
            fma2(Ar[1], wr0, v0.y); fma2(Az[1], wz0, v0.y); fma2(Ah[1], wg0, v0.y);
            fma2(Ar[2], wr0, v1.x); fma2(Az[2], wz0, v1.x); fma2(Ah[2], wg0, v1.x);
            fma2(Ar[3], wr0, v1.y); fma2(Az[3], wz0, v1.y); fma2(Ah[3], wg0, v1.y);
            fma2(Ar[0], wr1, u0.x); fma2(Az[0], wz1, u0.x); fma2(Ah[0], wg1, u0.x);
            fma2(Ar[1], wr1, u0.y); fma2(Az[1], wz1, u0.y); fma2(Ah[1], wg1, u0.y);
            fma2(Ar[2], wr1, u1.x); fma2(Az[2], wz1, u1.x); fma2(Ah[2], wg1, u1.x);
            fma2(Ar[3], wr1, u1.y); fma2(Az[3], wz1, u1.y); fma2(Ah[3], wg1, u1.y);
        }

        float hnew[8];
        {
            const ull* hj = (const ull*)&h_s[j][rbase];
#pragma unroll
            for (int p = 0; p < 4; p++) {
                float2 fr = unpack2(Ar[p]), fz = unpack2(Az[p]);
                float2 fg = unpack2(Ag[p]), fh = unpack2(Ah[p]);
                float2 ho = unpack2(hj[p]);
                {
                    float r = fsig(fr.x), z = fsig(fz.x);
                    float g = ftanh(fg.x + r * (fh.x + bn));
                    hnew[2 * p] = (1.f - z) * g + z * ho.x;
                }
                {
                    float r = fsig(fr.y), z = fsig(fz.y);
                    float g = ftanh(fg.y + r * (fh.y + bn));
                    hnew[2 * p + 1] = (1.f - z) * g + z * ho.y;
                }
            }
        }
        __syncthreads();
#pragma unroll
        for (int m = 0; m < 8; m++) h_s[j][rbase + m] = hnew[m];
    }
    __syncthreads();

    // ================= projection: ctx -> inp_s[25..88] (fp32) =================
    {
        const int jc = tid & 63, rg2 = tid >> 6;
        const float pb = proj_b[jc];
#pragma unroll
        for (int m = 0; m < 4; m++) {
            int r = rg2 * 4 + m;
            float acc = pb;
#pragma unroll 4
            for (int k = 0; k < 128; k++) acc += h_s[k][r] * g_projT[k * 64 + jc];
            inp_s[25 + jc][r] = acc;
        }
    }
    // sigma_0 = sym(context[:, T-1])
    for (int i = tid; i < RPB * 25; i += 256) {
        int r = i / 25, k = i - r * 25;
        int ii = k / 5, jj = k - ii * 5;
        const float* p = C + ((size_t)(b0 + r) * T_LEN + (T_LEN - 1)) * 25;
        inp_s[k][r] = 0.5f * (p[ii * 5 + jj] + p[jj * 5 + ii]);
    }
    __syncthreads();

    const float v_db0 = db0[j], v_db1 = db1[j], v_db2 = db2[j];
    const float v_fb0 = fb0[j], v_fb1 = fb1[j];

    // ================= SDE steps =================
    for (int step = 0; step < NSTEPS; step++) {
        mlp_layer(g_dr0P, 45, inp_s, b1_s, v_db0, j, rbase);
        __syncthreads();
        mlp_layer(g_dr1P, 64, b1_s, b2_s, v_db1, j, rbase);
        __syncthreads();
        mlp_layer(g_dr2P, 64, b2_s, b1_s, v_db2, j, rbase);
        __syncthreads();
        // drift L3 (240 items, fp32 weights) + diff L0 (all threads)
        {
            if (tid < 240) {
                int r = tid / 15, k = tid - r * 15;
                float acc = db3[k];
#pragma unroll 4
                for (int cc = 0; cc < 128; cc++) acc += b1_s[cc][r] * g_dr3T[cc * 15 + k];
                inp_s[89 + k][r] = acc;   // raw drift_c
            }
            mlp_layer(g_df0P, 45, inp_s, b2_s, v_fb0, j, rbase);
        }
        __syncthreads();
        mlp_layer(g_df1P, 64, b2_s, b1_s, v_fb1, j, rbase);
        __syncthreads();
        // diff L2 + combine: coeff = drift*DT + softplus(.)*dW
        if (tid < 240) {
            int r = tid / 15, k = tid - r * 15;
            float acc = fb2[k];
#pragma unroll 4
            for (int cc = 0; cc < 128; cc++) acc += b1_s[cc][r] * g_df2T[cc * 15 + k];
            float sp = (acc > 20.f) ? acc : log1pf(__expf(acc));
            float dwv = dW[((size_t)(b0 + r) * NSTEPS + step) * DDIM + k];
            inp_s[89 + k][r] = inp_s[89 + k][r] * DT_C + sp * dwv;
        }
        __syncthreads();
        if (tid < RPB) geo_update(&inp_s[0][tid]);
        __syncthreads();
    }

    for (int i = tid; i < RPB * 25; i += 256) {
        int r = i / 25, k = i - r * 25;
        out[(size_t)(b0 + r) * 25 + k] = inp_s[k][r];
    }
}

// ---------------- launch ---------------------------------------------------------
extern "C" void kernel_launch(void* const* d_in, const int* in_sizes, int n_in,
                              void* d_out, int out_size) {
    const float* ctx_spd = (const float*)d_in[0];
    const float* dWp     = (const float*)d_in[1];
    const float* wih     = (const float*)d_in[2];
    const float* whh     = (const float*)d_in[3];
    const float* gbias   = (const float*)d_in[4];
    const float* gbias_n = (const float*)d_in[5];
    const float* projw   = (const float*)d_in[6];
    const float* projb   = (const float*)d_in[7];
    const float* dw0 = (const float*)d_in[8];  const float* db0 = (const float*)d_in[9];
    const float* dw1 = (const float*)d_in[10]; const float* db1 = (const float*)d_in[11];
    const float* dw2 = (const float*)d_in[12]; const float* db2 = (const float*)d_in[13];
    const float* dw3 = (const float*)d_in[14]; const float* db3 = (const float*)d_in[15];
    const float* fw0 = (const float*)d_in[16]; const float* fb0 = (const float*)d_in[17];
    const float* fw1 = (const float*)d_in[18]; const float* fb1 = (const float*)d_in[19];
    const float* fw2 = (const float*)d_in[20]; const float* fb2 = (const float*)d_in[21];
    float* out = (float*)d_out;

    prep_kernel<<<64, 256>>>(wih, whh, projw, dw0, dw1, dw2, dw3, fw0, fw1, fw2);
    fused_kernel<<<NBLK, 256>>>(ctx_spd, dWp, gbias, gbias_n, projb,
                                db0, db1, db2, db3, fb0, fb1, fb2, out);
}